// round 5
// baseline (speedup 1.0000x reference)
#include <cuda_runtime.h>

#define BNUM  32
#define TENC  4096
#define TPRED 1024
#define DHALF 512
#define DFULL 1024
#define NCLS  4
#define ENC_TS  32     // 4096 / 128
#define PRED_TS 8      // 1024 / 128
#define NSPLIT  (ENC_TS + PRED_TS)   // 40 CTAs per b
#define TCHUNK  128
#define LN_EPS 1e-5f

__device__ float g_part_e[ENC_TS  * BNUM * NCLS * DHALF];  // 8 MB
__device__ float g_part_p[PRED_TS * BNUM * NCLS * DHALF];  // 2 MB
__device__ float g_loss_b[BNUM];
__device__ unsigned int g_ticket_b[BNUM];
__device__ unsigned int g_ticket;

// ---------------------------------------------------------------------------
// Single fused kernel. grid (NSPLIT, BNUM), 128 threads.
// Phase 1 (all CTAs): masked partial sums for one (b, t-chunk).
// Phase 2 (last CTA per b via ticket): counts + split-reduce + LN + logits
//         + per-b loss; last b overall writes the scalar.
// ---------------------------------------------------------------------------
__global__ void __launch_bounds__(128)
fused_kernel(const float4* __restrict__ enc,
             const float4* __restrict__ pred,
             const int*    __restrict__ lab_e,
             const int*    __restrict__ lab_p,
             const int*    __restrict__ label,
             const float*  __restrict__ norm_w,
             const float*  __restrict__ norm_b,
             const float*  __restrict__ head_w,
             const float*  __restrict__ head_b,
             float*        __restrict__ out) {
    int ts  = blockIdx.x;
    int b   = blockIdx.y;
    int tid = threadIdx.x;
    int lane = tid & 31, wid = tid >> 5;   // 4 warps

    // ======================= Phase 1: masked partial sums ==================
    {
        const float4* x;
        const int*    lab;
        float4*       pp;
        int T, tsl;
        if (ts < ENC_TS) {
            x = enc;  lab = lab_e; pp = (float4*)g_part_e; T = TENC;  tsl = ts;
        } else {
            x = pred; lab = lab_p; pp = (float4*)g_part_p; T = TPRED; tsl = ts - ENC_TS;
        }
        int t0 = tsl * TCHUNK;

        __shared__ int slab[TCHUNK];
        slab[tid] = lab[(size_t)b * T + t0 + tid];
        __syncthreads();

        const float4* xp = x + ((size_t)b * T + t0) * (DHALF / 4) + tid;

        float4 a0 = {0.f,0.f,0.f,0.f};
        float4 a1 = {0.f,0.f,0.f,0.f};
        float4 a2 = {0.f,0.f,0.f,0.f};
        float4 a3 = {0.f,0.f,0.f,0.f};

        #pragma unroll 8
        for (int t = 0; t < TCHUNK; ++t) {
            float4 v = __ldcs(&xp[(size_t)t * (DHALF / 4)]);
            int c = slab[t];
            a0.x += (c == 0) ? v.x : 0.f;  a0.y += (c == 0) ? v.y : 0.f;
            a0.z += (c == 0) ? v.z : 0.f;  a0.w += (c == 0) ? v.w : 0.f;
            a1.x += (c == 1) ? v.x : 0.f;  a1.y += (c == 1) ? v.y : 0.f;
            a1.z += (c == 1) ? v.z : 0.f;  a1.w += (c == 1) ? v.w : 0.f;
            a2.x += (c == 2) ? v.x : 0.f;  a2.y += (c == 2) ? v.y : 0.f;
            a2.z += (c == 2) ? v.z : 0.f;  a2.w += (c == 2) ? v.w : 0.f;
            a3.x += (c == 3) ? v.x : 0.f;  a3.y += (c == 3) ? v.y : 0.f;
            a3.z += (c == 3) ? v.z : 0.f;  a3.w += (c == 3) ? v.w : 0.f;
        }

        size_t base = (((size_t)tsl * BNUM + b) * NCLS) * (DHALF / 4) + tid;
        pp[base + 0 * (DHALF / 4)] = a0;
        pp[base + 1 * (DHALF / 4)] = a1;
        pp[base + 2 * (DHALF / 4)] = a2;
        pp[base + 3 * (DHALF / 4)] = a3;
    }

    // ======================= ticket: last CTA per b ========================
    __threadfence();
    __syncthreads();
    __shared__ int s_win;
    if (tid == 0) {
        unsigned int t = atomicAdd(&g_ticket_b[b], 1u);
        s_win = (t == NSPLIT - 1);
        if (s_win) g_ticket_b[b] = 0;    // reset for next replay
    }
    __syncthreads();
    if (!s_win) return;
    __threadfence();                      // acquire partials

    // ======================= Phase 2: finisher for b =======================
    // counts (enc: 32 ints/thread, pred: 8)
    __shared__ float s_inv[2][NCLS];
    {
        int ce[NCLS] = {0,0,0,0}, cp[NCLS] = {0,0,0,0};
        #pragma unroll 8
        for (int i = tid; i < TENC; i += 128) {
            int v = lab_e[(size_t)b * TENC + i];
            ce[0] += (v == 0); ce[1] += (v == 1); ce[2] += (v == 2); ce[3] += (v == 3);
        }
        #pragma unroll
        for (int i = tid; i < TPRED; i += 128) {
            int v = lab_p[(size_t)b * TPRED + i];
            cp[0] += (v == 0); cp[1] += (v == 1); cp[2] += (v == 2); cp[3] += (v == 3);
        }
        __shared__ int s_cw[2][4][NCLS];
        #pragma unroll
        for (int k = 0; k < NCLS; ++k) {
            #pragma unroll
            for (int o = 16; o; o >>= 1) {
                ce[k] += __shfl_xor_sync(0xffffffffu, ce[k], o);
                cp[k] += __shfl_xor_sync(0xffffffffu, cp[k], o);
            }
            if (lane == 0) { s_cw[0][wid][k] = ce[k]; s_cw[1][wid][k] = cp[k]; }
        }
        __syncthreads();
        if (tid < 2 * NCLS) {
            int h = tid >> 2, k = tid & 3;
            int tot = s_cw[h][0][k] + s_cw[h][1][k] + s_cw[h][2][k] + s_cw[h][3][k];
            s_inv[h][k] = 1.f / fmaxf((float)tot, 1.f);
        }
        __syncthreads();
    }

    // split-reduce -> per-thread means in registers.
    // thread owns float4 slot tid of each half: enc d=[tid*4), pred d=512+tid*4
    float4 fe[NCLS], fp[NCLS];
    {
        size_t stride = (size_t)BNUM * NCLS * (DHALF / 4);
        #pragma unroll
        for (int c = 0; c < NCLS; ++c) {
            size_t base = ((size_t)b * NCLS + c) * (DHALF / 4) + tid;
            float4 acc = {0.f,0.f,0.f,0.f};
            #pragma unroll 8
            for (int s = 0; s < ENC_TS; ++s) {
                float4 v = ((const float4*)g_part_e)[(size_t)s * stride + base];
                acc.x += v.x; acc.y += v.y; acc.z += v.z; acc.w += v.w;
            }
            float inv = s_inv[0][c];
            acc.x *= inv; acc.y *= inv; acc.z *= inv; acc.w *= inv;
            fe[c] = acc;

            float4 accp = {0.f,0.f,0.f,0.f};
            #pragma unroll
            for (int s = 0; s < PRED_TS; ++s) {
                float4 v = ((const float4*)g_part_p)[(size_t)s * stride + base];
                accp.x += v.x; accp.y += v.y; accp.z += v.z; accp.w += v.w;
            }
            inv = s_inv[1][c];
            accp.x *= inv; accp.y *= inv; accp.z *= inv; accp.w *= inv;
            fp[c] = accp;
        }
    }

    // LayerNorm stats over 1024 per class (each thread holds 8 values/class)
    __shared__ float s_red[2 * NCLS][4];
    __shared__ float s_mu[NCLS], s_rstd[NCLS];
    #pragma unroll
    for (int c = 0; c < NCLS; ++c) {
        float s = fe[c].x + fe[c].y + fe[c].z + fe[c].w
                + fp[c].x + fp[c].y + fp[c].z + fp[c].w;
        float q = fe[c].x*fe[c].x + fe[c].y*fe[c].y + fe[c].z*fe[c].z + fe[c].w*fe[c].w
                + fp[c].x*fp[c].x + fp[c].y*fp[c].y + fp[c].z*fp[c].z + fp[c].w*fp[c].w;
        #pragma unroll
        for (int o = 16; o; o >>= 1) {
            s += __shfl_xor_sync(0xffffffffu, s, o);
            q += __shfl_xor_sync(0xffffffffu, q, o);
        }
        if (lane == 0) { s_red[c * 2][wid] = s; s_red[c * 2 + 1][wid] = q; }
    }
    __syncthreads();
    if (tid < NCLS) {
        float s = s_red[tid*2][0] + s_red[tid*2][1] + s_red[tid*2][2] + s_red[tid*2][3];
        float q = s_red[tid*2+1][0] + s_red[tid*2+1][1] + s_red[tid*2+1][2] + s_red[tid*2+1][3];
        float mu  = s / (float)DFULL;
        float var = q / (float)DFULL - mu * mu;
        s_mu[tid]   = mu;
        s_rstd[tid] = rsqrtf(var + LN_EPS);
    }
    __syncthreads();

    // normalize + partial logits over the thread's 8 d's
    __shared__ float s_lg[4][NCLS][NCLS];
    __shared__ float s_logits[NCLS][NCLS];
    {
        int ge = tid * 4, gp = DHALF + tid * 4;
        float4 we = *(const float4*)(norm_w + ge);
        float4 wp = *(const float4*)(norm_w + gp);
        float4 be = *(const float4*)(norm_b + ge);
        float4 bp = *(const float4*)(norm_b + gp);
        float4 hwe[NCLS], hwp[NCLS];
        #pragma unroll
        for (int n = 0; n < NCLS; ++n) {
            hwe[n] = *(const float4*)(head_w + (size_t)n * DFULL + ge);
            hwp[n] = *(const float4*)(head_w + (size_t)n * DFULL + gp);
        }
        #pragma unroll
        for (int c = 0; c < NCLS; ++c) {
            float mu = s_mu[c], r = s_rstd[c];
            float ex = (fe[c].x - mu) * r * we.x + be.x;
            float ey = (fe[c].y - mu) * r * we.y + be.y;
            float ez = (fe[c].z - mu) * r * we.z + be.z;
            float ew = (fe[c].w - mu) * r * we.w + be.w;
            float px = (fp[c].x - mu) * r * wp.x + bp.x;
            float py = (fp[c].y - mu) * r * wp.y + bp.y;
            float pz = (fp[c].z - mu) * r * wp.z + bp.z;
            float pw = (fp[c].w - mu) * r * wp.w + bp.w;
            #pragma unroll
            for (int n = 0; n < NCLS; ++n) {
                float v = ex * hwe[n].x + ey * hwe[n].y + ez * hwe[n].z + ew * hwe[n].w
                        + px * hwp[n].x + py * hwp[n].y + pz * hwp[n].z + pw * hwp[n].w;
                #pragma unroll
                for (int o = 16; o; o >>= 1)
                    v += __shfl_xor_sync(0xffffffffu, v, o);
                if (lane == 0) s_lg[wid][c][n] = v;
            }
        }
    }
    __syncthreads();
    if (tid < NCLS * NCLS) {
        int c = tid >> 2, n = tid & 3;
        s_logits[c][n] = s_lg[0][c][n] + s_lg[1][c][n] + s_lg[2][c][n] + s_lg[3][c][n]
                       + head_b[n];
    }
    __syncthreads();

    if (tid == 0) {
        float sel_sum = 0.f;
        #pragma unroll
        for (int l = 0; l < NCLS; ++l) {
            int lb = label[b * NCLS + l];
            float m = s_logits[lb][0];
            #pragma unroll
            for (int n = 1; n < NCLS; ++n) m = fmaxf(m, s_logits[lb][n]);
            float se = 0.f;
            #pragma unroll
            for (int n = 0; n < NCLS; ++n) se += expf(s_logits[lb][n] - m);
            sel_sum += s_logits[lb][lb] - m - logf(se);
        }
        g_loss_b[b] = sel_sum;
        __threadfence();
        unsigned int t = atomicAdd(&g_ticket, 1u);
        if (t == BNUM - 1) {
            float tot = 0.f;
            #pragma unroll
            for (int i = 0; i < BNUM; ++i) tot += g_loss_b[i];
            out[0] = -tot / (float)(BNUM * NCLS);
            g_ticket = 0;   // reset for next replay
        }
    }
}

// ---------------------------------------------------------------------------
extern "C" void kernel_launch(void* const* d_in, const int* in_sizes, int n_in,
                              void* d_out, int out_size) {
    const float* enc_out = (const float*)d_in[0];
    const float* pred_out = (const float*)d_in[1];
    const int*   frame_label  = (const int*)d_in[2];
    const int*   frame_tlabel = (const int*)d_in[3];
    const int*   label  = (const int*)d_in[4];
    const float* norm_w = (const float*)d_in[5];
    const float* norm_b = (const float*)d_in[6];
    const float* head_w = (const float*)d_in[7];
    const float* head_b = (const float*)d_in[8];
    float* out = (float*)d_out;

    fused_kernel<<<dim3(NSPLIT, BNUM), 128>>>(
        (const float4*)enc_out, (const float4*)pred_out,
        frame_label, frame_tlabel, label,
        norm_w, norm_b, head_w, head_b, out);
}